// round 16
// baseline (speedup 1.0000x reference)
#include <cuda_runtime.h>
#include <cstdint>

// Problem constants (fixed by the reference)
#define B_ 32
#define S_ 512
#define P_ 8
#define K_ 256
#define D_ 64
#define NROWS (B_ * S_ * P_)   // 131072 rows of K=256 logits each

#define FULL 0xffffffffu
#define NEG_INF __int_as_float(0xff800000)
#define LN2F 0.69314718055994530942f
#define TINYF 1.17549435e-38f

__device__ __forceinline__ uint32_t rotl32(uint32_t x, int r) {
    return __funnelshift_l(x, x, r);
}
__device__ __forceinline__ float lg2a(float x) {
    float r;
    asm("lg2.approx.f32 %0, %1;" : "=f"(r) : "f"(x));
    return r;
}

// ---------------------------------------------------------------------------
// JAX threefry2x32, partitionable mode, key (0, 42); counter = (0, i).
// Draw = x0 ^ x1. ks = (0, 42, 0x1BD11BDA^42). Plain SHF/LOP3/IADD core —
// R5/R8/R11/R12 measured that touching this serial chain loses.
// ---------------------------------------------------------------------------
__device__ __forceinline__ uint32_t threefry_bits(uint32_t i) {
    const uint32_t KS1 = 42u;
    const uint32_t KS2 = 0x1BD11BDAu ^ 42u;
    uint32_t x1 = i + KS1;
    uint32_t x0 = x1;                  // round 1: x0 = 0 + x1
    x1 = rotl32(x1, 13) ^ x0;
#define RND(r) { x0 += x1; x1 = rotl32(x1, (r)) ^ x0; }
    RND(15) RND(26) RND(6)
    x0 += KS1;  x1 += KS2 + 1u;
    RND(17) RND(29) RND(16) RND(24)
    x0 += KS2;  x1 += 2u;              // ks0 = 0
    RND(13) RND(15) RND(26) RND(6)
    /* x0 += ks0 == 0 */ x1 += KS1 + 3u;
    RND(17) RND(29) RND(16) RND(24)
    x0 += KS1;  x1 += KS2 + 4u;
    RND(13) RND(15) RND(26) RND(6)
    x0 += KS2;  x1 += 5u;
#undef RND
    return x0 ^ x1;
}

// Exact path: bit-identical to the reference fp32 computation (accurate logf).
// (f + TINYF == fmaxf(f, tiny) for every representable f in {0} U [2^-23, 1).)
__device__ __forceinline__ float exact_score(const float* __restrict__ erow,
                                             uint32_t row_base, int k) {
    uint32_t bits = threefry_bits(row_base + (uint32_t)k);
    float f = __uint_as_float((bits >> 9) | 0x3f800000u) - 1.0f;  // u in [0,1)
    float u = f + TINYF;
    float g = -logf(-logf(u));
    return __ldg(erow + k) + g;
}

// One fast-screen element: s = e - ln2 * lg2a(-lg2a(u))
__device__ __forceinline__ float screen1(uint32_t idx, float e) {
    uint32_t bits = threefry_bits(idx);
    float f  = __uint_as_float((bits >> 9) | 0x3f800000u) - 1.0f;
    float u  = f + TINYF;
    float l1 = lg2a(u);
    float t  = lg2a(-l1);
    return fmaf(t, -LN2F, e);
}

// Warp max of a lane value via REDUX on order-preserving uint map.
__device__ __forceinline__ float warp_max(float lmax) {
    uint32_t ub = __float_as_uint(lmax);
    ub ^= (uint32_t)((int32_t)ub >> 31) | 0x80000000u;
    uint32_t um = __reduce_max_sync(FULL, ub);
    um ^= ~(uint32_t)((int32_t)um >> 31) | 0x80000000u;
    return __uint_as_float(um);
}

// Band + unique test + (rare) bit-exact fallback. Returns argmax index.
__device__ __forceinline__ int resolve(const float* s, float smax, int lane,
                                       const float* __restrict__ erow,
                                       uint32_t row_base) {
    const float thr = smax - 4e-4f;
    uint32_t mask = 0;
#pragma unroll
    for (int j = 0; j < 8; j++)
        if (s[j] >= thr) mask |= (1u << j);
    const int tot = __reduce_add_sync(FULL, __popc(mask));

    int bestk;
    if (tot == 1) {
        unsigned ball = __ballot_sync(FULL, mask != 0);
        int owner = __ffs(ball) - 1;
        int jm = __ffs(mask) - 1;            // valid on owner lane
        bestk = __shfl_sync(FULL, lane * 8 + jm, owner);
    } else {
        // Rare (~50/131072 rows): exact (reference-identical) scores on band.
        float bestx = NEG_INF;
        bestk = K_;
#pragma unroll
        for (int j = 0; j < 8; j++) {
            bool cand = (mask >> j) & 1u;
            if (__any_sync(FULL, cand)) {
                int   k = lane * 8 + j;
                float x = NEG_INF;
                if (cand) x = exact_score(erow, row_base, k);
                if (x > bestx || (x == bestx && k < bestk)) { bestx = x; bestk = k; }
            }
        }
#pragma unroll
        for (int off = 16; off > 0; off >>= 1) {
            float ob = __shfl_xor_sync(FULL, bestx, off);
            int   ok = __shfl_xor_sync(FULL, bestk, off);
            if (ob > bestx || (ob == bestx && ok < bestk)) { bestx = ob; bestk = ok; }
        }
    }
    return bestk;
}

// ---------------------------------------------------------------------------
// TWO rows per warp (2w, 2w+1), software-pipelined tails (R15), with row-A
// scores parked in SMEM ([j][tid] layout: conflict-free) so peak live regs
// stay <= 32 and occupancy returns to 8 blocks/SM. LSU pipe was idle; the
// 16 extra STS/LDS per row-pair are free slots.
// ---------------------------------------------------------------------------
__global__ void __launch_bounds__(256, 8) symbolic_gumbel_kernel(
    const int*   __restrict__ inputs,       // [B, S] int32
    const float* __restrict__ pattern_map,  // [N_CAT, P, K]
    const float* __restrict__ symbols,      // [K, D]
    float*       __restrict__ out)          // [B, S, P*D]
{
    __shared__ float sAsh[8][256];           // 8KB/block; [j][tid] -> no conflicts

    const int tid  = threadIdx.x;
    const int warp = (blockIdx.x * blockDim.x + tid) >> 5;
    const int lane = tid & 31;

    const int rowA = warp * 2;               // even -> pA in {0,2,4,6}
    const int bs   = rowA >> 3;
    const int pA   = rowA & 7;
    const int cat  = __ldg(&inputs[bs]);     // shared by rows A and B

    const float* erowA = pattern_map + ((size_t)cat * P_ + pA) * K_;
    const float* erowB = erowA + K_;         // pB = pA + 1, same bs
    const uint32_t rbA = (uint32_t)rowA * (uint32_t)K_;
    const uint32_t rbB = rbA + (uint32_t)K_;
    const uint32_t baseA = rbA + (uint32_t)(lane * 8);
    const uint32_t baseB = baseA + (uint32_t)K_;

    // Issue all energy loads upfront (independent; latency overlaps hash A).
    const float4* eA4 = reinterpret_cast<const float4*>(erowA + lane * 8);
    const float4* eB4 = reinterpret_cast<const float4*>(erowB + lane * 8);
    float4 a0 = __ldg(&eA4[0]);
    float4 a1 = __ldg(&eA4[1]);
    float4 b0 = __ldg(&eB4[0]);
    float4 b1 = __ldg(&eB4[1]);

    // ---- Row A screen: scores go to SMEM, only the running max stays live ----
    {
        float eA[8] = {a0.x, a0.y, a0.z, a0.w, a1.x, a1.y, a1.z, a1.w};
        float mA = NEG_INF;
#pragma unroll
        for (int j = 0; j < 8; j++) {
            float x = screen1(baseA + (uint32_t)j, eA[j]);
            sAsh[j][tid] = x;
            mA = fmaxf(mA, x);
        }
        // REDUX A issues; its latency hides under the start of hash B.
        const float smaxA = warp_max(mA);

        // ---- Row B screen (dense alu stream covers REDUX-A latency) ----
        float sB[8];
        float mB = NEG_INF;
#pragma unroll
        for (int j = 0; j < 8; j++) {
            float x = screen1(baseB + (uint32_t)j, eB4 ? ((j < 4) ? (&b0.x)[j] : (&b1.x)[j - 4]) : 0.0f);
            sB[j] = x;
            mB = fmaxf(mB, x);
        }

        // Reload row-A scores (LDS lat 29, covered by surrounding stream).
        float sA[8];
#pragma unroll
        for (int j = 0; j < 8; j++) sA[j] = sAsh[j][tid];

        // ---- Resolve A, start its output load ----
        const int bestkA = resolve(sA, smaxA, lane, erowA, rbA);
        const float2* srowA = reinterpret_cast<const float2*>(symbols + (size_t)bestkA * D_);
        float2 valA = __ldg(&srowA[lane]);       // LDG in flight...

        // ...covered by REDUX B:
        const float smaxB = warp_max(mB);

        // Store A (waits on its LDG), then resolve + output B.
        float2* orowA = reinterpret_cast<float2*>(out + (size_t)rowA * D_);
        orowA[lane] = valA;

        const int bestkB = resolve(sB, smaxB, lane, erowB, rbB);
        const float2* srowB = reinterpret_cast<const float2*>(symbols + (size_t)bestkB * D_);
        float2 valB = __ldg(&srowB[lane]);
        float2* orowB = reinterpret_cast<float2*>(out + (size_t)(rowA + 1) * D_);
        orowB[lane] = valB;
    }
}

extern "C" void kernel_launch(void* const* d_in, const int* in_sizes, int n_in,
                              void* d_out, int out_size) {
    const int*   inputs      = (const int*)  d_in[0];  // [32, 512] int32
    const float* pattern_map = (const float*)d_in[1];  // [50000, 8, 256]
    const float* symbols     = (const float*)d_in[2];  // [256, 64]
    // d_in[3] = tau (== 1.0, positive): argmax invariant; straight-through
    // weights are one-hot to fp32 rounding, so tau is unused.
    float* out = (float*)d_out;                        // [32, 512, 512]

    const int threads = 256;                 // 8 warps -> 16 rows per block
    const int blocks  = NROWS / 16;          // 8192
    symbolic_gumbel_kernel<<<blocks, threads>>>(inputs, pattern_map, symbols, out);
}